// round 11
// baseline (speedup 1.0000x reference)
#include <cuda_runtime.h>
#include <cuda_bf16.h>
#include <cstdint>
#include <cstddef>

#define TB      8192
#define CIN     3
#define HH      23
#define WWID    30
#define COUT    8
#define OH      22
#define OW      29
#define K1      5104
#define KP      5120
#define KP2     (2 * KP)            // interleaved hi|lo row length (bf16 elems)
#define NF1     64
#define NS      32
#define NN      19
#define UNFOLDS 6
#define CHUNK   16
#define WARM    5
#define L2E     1.4426950408889634f

#define MT      64
#define NCHUNK  80
#define SPLITK  4
#define CPS     (NCHUNK / SPLITK)   // 20
#define SPB     144
#define ARR     (MT * SPB)          // 9216 bytes per stage array
#define STAGE4  (4 * ARR)           // 36864 per buffer
#define GSMEM   (2 * STAGE4)        // 73728 dynamic smem

// interleaved pre-split operands: [row][chunk][64 hi | 64 lo]
__device__ __nv_bfloat16 g_a[(size_t)TB * KP2];
__device__ __nv_bfloat16 g_b[(size_t)NF1 * KP2];
__device__ float g_part[(size_t)SPLITK * TB * NF1];
__device__ float g_wns[(size_t)TB * NN];
__device__ float g_wds[(size_t)TB * NN];
__device__ float g_r_s2[NN * NN], g_r_c2[NN * NN], g_r_he[NN * NN], g_r_hp[NN * NN];
__device__ float g_s_s2[NS * NN], g_s_c2[NS * NN], g_s_he[NS * NN], g_s_hp[NS * NN];
__device__ float g_cmt[NN], g_Aj[NN], g_Dj[NN];

__device__ __forceinline__ float ex2f(float x) { float y; asm("ex2.approx.f32 %0, %1;" : "=f"(y) : "f"(x)); return y; }
__device__ __forceinline__ float rcpf(float x) { float y; asm("rcp.approx.f32 %0, %1;" : "=f"(y) : "f"(x)); return y; }
__device__ __forceinline__ uint32_t smem_u32(const void* p) {
    uint32_t a;
    asm("{ .reg .u64 t; cvta.to.shared.u64 t, %1; cvt.u32.u64 %0, t; }" : "=r"(a) : "l"(p));
    return a;
}
__device__ __forceinline__ void ldm_x4(uint32_t* r, uint32_t addr) {
    asm volatile("ldmatrix.sync.aligned.m8n8.x4.shared.b16 {%0,%1,%2,%3}, [%4];"
                 : "=r"(r[0]), "=r"(r[1]), "=r"(r[2]), "=r"(r[3]) : "r"(addr));
}
__device__ __forceinline__ void mma16816(float* c, const uint32_t* a, uint32_t b0, uint32_t b1) {
    asm volatile("mma.sync.aligned.m16n8k16.row.col.f32.bf16.bf16.f32 "
                 "{%0,%1,%2,%3}, {%4,%5,%6,%7}, {%8,%9}, {%0,%1,%2,%3};"
                 : "+f"(c[0]), "+f"(c[1]), "+f"(c[2]), "+f"(c[3])
                 : "r"(a[0]), "r"(a[1]), "r"(a[2]), "r"(a[3]), "r"(b0), "r"(b1));
}

__global__ void precompute_kernel(
    const float* __restrict__ w_, const float* __restrict__ mu_, const float* __restrict__ sig_,
    const float* __restrict__ erev_, const float* __restrict__ mask_,
    const float* __restrict__ sw, const float* __restrict__ smu, const float* __restrict__ ssig,
    const float* __restrict__ serev, const float* __restrict__ smask,
    const float* __restrict__ gleak, const float* __restrict__ vleak, const float* __restrict__ cm_)
{
    int t = threadIdx.x;
    if (t < NN * NN) {
        float wp = log1pf(expf(w_[t])) * mask_[t];
        g_r_s2[t] = -sig_[t] * L2E;
        g_r_c2[t] = sig_[t] * mu_[t] * L2E;
        g_r_he[t] = wp * erev_[t];
        g_r_hp[t] = wp;
    }
    if (t < NS * NN) {
        float sp = log1pf(expf(sw[t]));
        g_s_s2[t] = -ssig[t] * L2E;
        g_s_c2[t] = ssig[t] * smu[t] * L2E;
        g_s_he[t] = sp * serev[t];
        g_s_hp[t] = sp * smask[t];
    }
    if (t < NN) {
        float cmt = log1pf(expf(cm_[t])) * (float)UNFOLDS;
        float g = log1pf(expf(gleak[t]));
        g_cmt[t] = cmt;
        g_Aj[t] = g * vleak[t];
        g_Dj[t] = cmt + g + 1e-8f;
    }
}

__global__ __launch_bounds__(256) void bsplit_kernel(const float* __restrict__ fc1w) {
    int row = blockIdx.x;
    for (int k = threadIdx.x; k < KP; k += 256) {
        float v = (k < K1) ? fc1w[(size_t)row * K1 + k] : 0.f;
        __nv_bfloat16 h = __float2bfloat16(v);
        __nv_bfloat16 l = __float2bfloat16(v - __bfloat162float(h));
        size_t base = (size_t)row * KP2 + (size_t)(k >> 6) * 128 + (k & 63);
        g_b[base] = h;
        g_b[base + 64] = l;
    }
}

__global__ __launch_bounds__(256) void conv_kernel(
    const float* __restrict__ x, const float* __restrict__ cw, const float* __restrict__ cb)
{
    __shared__ float sx[CIN * HH * WWID];
    __shared__ float swt[COUT * CIN * 4];
    __shared__ float sb[COUT];
    int b = blockIdx.x;
    const float* xb = x + (size_t)b * (CIN * HH * WWID);
    for (int i = threadIdx.x; i < CIN * HH * WWID; i += 256) sx[i] = xb[i];
    if (threadIdx.x < COUT * CIN * 4) swt[threadIdx.x] = cw[threadIdx.x];
    if (threadIdx.x < COUT) sb[threadIdx.x] = cb[threadIdx.x];
    __syncthreads();
    __nv_bfloat16* oa = g_a + (size_t)b * KP2;
    for (int idx = threadIdx.x; idx < COUT * OH * OW; idx += 256) {
        int c = idx / (OH * OW);
        int rem = idx - c * (OH * OW);
        int r = rem / OW;
        int col = rem - r * OW;
        float acc = sb[c];
        #pragma unroll
        for (int ci = 0; ci < CIN; ci++)
            #pragma unroll
            for (int kh = 0; kh < 2; kh++)
                #pragma unroll
                for (int kw = 0; kw < 2; kw++)
                    acc = fmaf(sx[ci * (HH * WWID) + (r + kh) * WWID + col + kw],
                               swt[((c * CIN + ci) * 2 + kh) * 2 + kw], acc);
        float y = acc > 0.f ? acc : expm1f(acc);
        __nv_bfloat16 h = __float2bfloat16(y);
        size_t base = (size_t)(idx >> 6) * 128 + (idx & 63);
        oa[base] = h;
        oa[base + 64] = __float2bfloat16(y - __bfloat162float(h));
    }
    if (threadIdx.x < KP - K1) {   // zero pad tail of chunk 79
        int k = K1 + threadIdx.x;
        size_t base = (size_t)(k >> 6) * 128 + (k & 63);
        oa[base] = __float2bfloat16(0.f);
        oa[base + 64] = __float2bfloat16(0.f);
    }
}

// fc1 split-K GEMM, double-buffered smem; grid (128, SPLITK); fp32 partials out
__global__ __launch_bounds__(256, 3) void gemm_kernel()
{
    extern __shared__ __align__(16) uint8_t sStage[];   // 2 buffers x 4 arrays

    const int tid = threadIdx.x;
    const int wid = tid >> 5;
    const int lid = tid & 31;
    const int wm = wid & 3;
    const int wn = wid >> 2;
    const int m0 = blockIdx.x * MT;
    const int c0 = blockIdx.y * CPS;
    const uint32_t sb = smem_u32(sStage);

    const uint32_t aRow = (uint32_t)((lid & 7) + 8 * ((lid >> 3) & 1));
    const uint32_t aOff = (uint32_t)((wm * 16 + aRow) * SPB + (lid >> 4) * 16);
    const uint32_t bRow0 = (uint32_t)(wn * 32 + (lid & 7) + 8 * (lid >> 4));
    const uint32_t bKh = (uint32_t)(((lid >> 3) & 1) * 16);
    const uint32_t bOff0 = bRow0 * SPB + bKh;
    const uint32_t bOff1 = (bRow0 + 16) * SPB + bKh;

    int prow[2], po8[2];
    #pragma unroll
    for (int p = 0; p < 2; p++) { int id = tid + 256 * p; prow[p] = id >> 3; po8[p] = id & 7; }

    float acc[4][4];
    #pragma unroll
    for (int nb = 0; nb < 4; nb++)
        #pragma unroll
        for (int q = 0; q < 4; q++) acc[nb][q] = 0.f;

    uint4 rah[2], ral[2], rbh[2], rbl[2];
    auto ld_chunk = [&](int c) {
        #pragma unroll
        for (int p = 0; p < 2; p++) {
            size_t ga = (size_t)(m0 + prow[p]) * KP2 + (size_t)c * 128 + po8[p] * 8;
            size_t gb = (size_t)prow[p] * KP2 + (size_t)c * 128 + po8[p] * 8;
            rah[p] = *(const uint4*)(g_a + ga);
            ral[p] = *(const uint4*)(g_a + ga + 64);
            rbh[p] = *(const uint4*)(g_b + gb);
            rbl[p] = *(const uint4*)(g_b + gb + 64);
        }
    };
    auto sts_buf = [&](int bufsel) {
        uint8_t* bb = sStage + bufsel * STAGE4;
        #pragma unroll
        for (int p = 0; p < 2; p++) {
            uint32_t so = (uint32_t)(prow[p] * SPB + po8[p] * 16);
            *(uint4*)(bb + so) = rah[p];
            *(uint4*)(bb + ARR + so) = ral[p];
            *(uint4*)(bb + 2 * ARR + so) = rbh[p];
            *(uint4*)(bb + 3 * ARR + so) = rbl[p];
        }
    };

    ld_chunk(c0);
    sts_buf(0);
    __syncthreads();

    for (int ci = 0; ci < CPS; ++ci) {
        if (ci + 1 < CPS) ld_chunk(c0 + ci + 1);
        const uint32_t B = sb + (uint32_t)((ci & 1) * STAGE4);
        const uint32_t AH = B, AL = B + ARR, BH = B + 2 * ARR, BL = B + 3 * ARR;
        #pragma unroll
        for (int s = 0; s < 4; ++s) {
            const uint32_t ks = (uint32_t)(32 * s);
            uint32_t ah[4], al[4], bh[8], bl[8];
            ldm_x4(ah, AH + aOff + ks);
            ldm_x4(al, AL + aOff + ks);
            ldm_x4(bh, BH + bOff0 + ks);
            ldm_x4(bh + 4, BH + bOff1 + ks);
            ldm_x4(bl, BL + bOff0 + ks);
            ldm_x4(bl + 4, BL + bOff1 + ks);
            #pragma unroll
            for (int nb = 0; nb < 4; ++nb) {
                mma16816(acc[nb], ah, bh[2 * nb], bh[2 * nb + 1]);
                mma16816(acc[nb], ah, bl[2 * nb], bl[2 * nb + 1]);
                mma16816(acc[nb], al, bh[2 * nb], bh[2 * nb + 1]);
            }
        }
        if (ci + 1 < CPS) sts_buf((ci + 1) & 1);
        __syncthreads();
    }

    {
        int gid = lid >> 2, tig = lid & 3;
        int r0 = wm * 16 + gid;
        float* pb = g_part + ((size_t)blockIdx.y * TB + m0) * NF1;
        #pragma unroll
        for (int nb = 0; nb < 4; ++nb) {
            int col = wn * 32 + nb * 8 + 2 * tig;
            *(float2*)(pb + (size_t)r0 * NF1 + col) = make_float2(acc[nb][0], acc[nb][1]);
            *(float2*)(pb + (size_t)(r0 + 8) * NF1 + col) = make_float2(acc[nb][2], acc[nb][3]);
        }
    }
}

__global__ __launch_bounds__(256) void epi_kernel(
    const float* __restrict__ fc1b,
    const float* __restrict__ fc2w, const float* __restrict__ fc2b,
    const float* __restrict__ inw, const float* __restrict__ inb)
{
    __shared__ float sAcc[64 * 68];
    __shared__ float sS[64 * 33];
    __shared__ float sF2[NS * NF1];
    __shared__ float sSm[160];
    __shared__ float sp[4 * NS * NN];

    const int tid = threadIdx.x;
    const int m0 = blockIdx.x * 64;

    for (int i = tid; i < NS * NF1; i += 256) sF2[i] = fc2w[i];
    if (tid < 64) sSm[tid] = fc1b[tid];
    if (tid < 32) { sSm[64 + tid] = fc2b[tid]; sSm[96 + tid] = inw[tid]; sSm[128 + tid] = inb[tid]; }
    for (int i = tid; i < NS * NN; i += 256) {
        sp[i] = g_s_s2[i];
        sp[NS * NN + i] = g_s_c2[i];
        sp[2 * NS * NN + i] = g_s_he[i];
        sp[3 * NS * NN + i] = g_s_hp[i];
    }

    for (int idx = tid; idx < 64 * 16; idx += 256) {
        int row = idx >> 4, c4 = (idx & 15) * 4;
        float4 a = make_float4(0.f, 0.f, 0.f, 0.f);
        #pragma unroll
        for (int s = 0; s < SPLITK; s++) {
            float4 v = *(const float4*)(g_part + ((size_t)s * TB + m0 + row) * NF1 + c4);
            a.x += v.x; a.y += v.y; a.z += v.z; a.w += v.w;
        }
        sAcc[row * 68 + c4 + 0] = fmaxf(a.x + sSm[c4 + 0], 0.f);
        sAcc[row * 68 + c4 + 1] = fmaxf(a.y + sSm[c4 + 1], 0.f);
        sAcc[row * 68 + c4 + 2] = fmaxf(a.z + sSm[c4 + 2], 0.f);
        sAcc[row * 68 + c4 + 3] = fmaxf(a.w + sSm[c4 + 3], 0.f);
    }
    __syncthreads();

    {
        int row = tid >> 2, cg = tid & 3;
        #pragma unroll
        for (int q = 0; q < 8; q++) {
            int n2 = cg * 8 + q;
            float a = sSm[64 + n2];
            #pragma unroll
            for (int n = 0; n < 64; n++) a = fmaf(sAcc[row * 68 + n], sF2[n2 * 64 + n], a);
            sS[row * 33 + n2] = fmaf(a, sSm[96 + n2], sSm[128 + n2]);
        }
    }
    __syncthreads();

    {
        int row2 = tid & 63, jg = tid >> 6;
        for (int jj = 0; jj < 5; jj++) {
            int j = jg * 5 + jj;
            if (j < NN) {
                float wn = 0.f, wd = 0.f;
                #pragma unroll
                for (int s2 = 0; s2 < NS; s2++) {
                    float he = sp[2 * NS * NN + s2 * NN + j];
                    float hp = sp[3 * NS * NN + s2 * NN + j];
                    if (he == 0.f && hp == 0.f) continue;
                    float e = ex2f(fmaf(sS[row2 * 33 + s2], sp[s2 * NN + j], sp[NS * NN + s2 * NN + j]));
                    float rr = rcpf(1.f + e);
                    wn = fmaf(rr, he, wn);
                    wd = fmaf(rr, hp, wd);
                }
                g_wns[(size_t)(m0 + row2) * NN + j] = wn;
                g_wds[(size_t)(m0 + row2) * NN + j] = wd;
            }
        }
    }
}

__global__ __launch_bounds__(128) void ltc_kernel(
    const float* __restrict__ outw, const float* __restrict__ outb, float* __restrict__ out)
{
    const int w = threadIdx.x >> 5;
    const int j = threadIdx.x & 31;
    const int jc = j < NN ? j : NN - 1;
    const int c = blockIdx.x * 4 + w;

    float s2n[NN], c2n[NN], he[NN], hp[NN];
    #pragma unroll
    for (int i = 0; i < NN; i++) {
        s2n[i] = g_r_s2[i * NN + jc];
        c2n[i] = g_r_c2[i * NN + jc];
        he[i] = g_r_he[i * NN + jc];
        hp[i] = g_r_hp[i * NN + jc];
    }
    const float cmt = g_cmt[jc], Aj = g_Aj[jc], Dj = g_Dj[jc];
    const float ow = outw[0], ob = outb[0];

    const int tout = c * CHUNK;
    int t0 = tout - WARM; if (t0 < 0) t0 = 0;
    const int tend = tout + CHUNK;

    float v = 0.f;
    float wns = g_wns[(size_t)t0 * NN + jc];
    float wds = g_wds[(size_t)t0 * NN + jc];

    for (int t = t0; t < tend; ++t) {
        float wns_n = 0.f, wds_n = 0.f;
        if (t + 1 < tend) {
            wns_n = g_wns[(size_t)(t + 1) * NN + jc];
            wds_n = g_wds[(size_t)(t + 1) * NN + jc];
        }
        #pragma unroll 1
        for (int u = 0; u < UNFOLDS; u++) {
            float wn = wns, wd = wds;
            #pragma unroll
            for (int i = 0; i < NN; i++) {
                float vi = __shfl_sync(0xffffffffu, v, i);
                float e = ex2f(fmaf(vi, s2n[i], c2n[i]));
                float r = rcpf(1.f + e);
                wn = fmaf(r, he[i], wn);
                wd = fmaf(r, hp[i], wd);
            }
            v = (fmaf(cmt, v, Aj) + wn) * rcpf(Dj + wd);
        }
        if (t >= tout && j == 0) out[t] = fmaf(v, ow, ob);
        wns = wns_n; wds = wds_n;
    }
}

extern "C" void kernel_launch(void* const* d_in, const int* in_sizes, int n_in,
                              void* d_out, int out_size) {
    const float* x      = (const float*)d_in[0];
    const float* conv_w = (const float*)d_in[1];
    const float* conv_b = (const float*)d_in[2];
    const float* fc1_w  = (const float*)d_in[3];
    const float* fc1_b  = (const float*)d_in[4];
    const float* fc2_w  = (const float*)d_in[5];
    const float* fc2_b  = (const float*)d_in[6];
    const float* inw    = (const float*)d_in[7];
    const float* inb    = (const float*)d_in[8];
    const float* sw     = (const float*)d_in[9];
    const float* smu    = (const float*)d_in[10];
    const float* ssig   = (const float*)d_in[11];
    const float* serev  = (const float*)d_in[12];
    const float* smask  = (const float*)d_in[13];
    const float* w_     = (const float*)d_in[14];
    const float* mu_    = (const float*)d_in[15];
    const float* sig_   = (const float*)d_in[16];
    const float* erev_  = (const float*)d_in[17];
    const float* mask_  = (const float*)d_in[18];
    const float* gleak  = (const float*)d_in[19];
    const float* vleak  = (const float*)d_in[20];
    const float* cm_    = (const float*)d_in[21];
    const float* outw   = (const float*)d_in[22];
    const float* outb   = (const float*)d_in[23];
    float* out = (float*)d_out;

    cudaFuncSetAttribute(gemm_kernel, cudaFuncAttributeMaxDynamicSharedMemorySize, GSMEM);

    precompute_kernel<<<1, NS * NN>>>(w_, mu_, sig_, erev_, mask_,
                                      sw, smu, ssig, serev, smask,
                                      gleak, vleak, cm_);
    bsplit_kernel<<<NF1, 256>>>(fc1_w);
    conv_kernel<<<TB, 256>>>(x, conv_w, conv_b);
    gemm_kernel<<<dim3(TB / MT, SPLITK), 256, GSMEM>>>();
    epi_kernel<<<TB / 64, 256>>>(fc1_b, fc2_w, fc2_b, inw, inb);
    ltc_kernel<<<(TB / CHUNK) / 4, 128>>>(outw, outb, out);
}

// round 13
// speedup vs baseline: 1.2040x; 1.2040x over previous
#include <cuda_runtime.h>
#include <cuda_bf16.h>
#include <cstdint>
#include <cstddef>

#define TB      8192
#define CIN     3
#define HH      23
#define WWID    30
#define COUT    8
#define OH      22
#define OW      29
#define K1      5104
#define KP      5120
#define NF1     64
#define NS      32
#define NN      19
#define UNFOLDS 6
#define CHUNK   8
#define WARM    5
#define L2E     1.4426950408889634f

#define MT      64
#define NCHUNK  80
#define SPLITK  4
#define CPS     (NCHUNK / SPLITK)   // 20 chunks per split
#define SPB     144

__device__ __nv_bfloat16 g_ah[(size_t)TB * KP];
__device__ __nv_bfloat16 g_al[(size_t)TB * KP];
__device__ __nv_bfloat16 g_bh[(size_t)NF1 * KP];
__device__ __nv_bfloat16 g_bl[(size_t)NF1 * KP];
__device__ float g_part[(size_t)SPLITK * TB * NF1];
__device__ float g_wns[(size_t)TB * NN];
__device__ float g_wds[(size_t)TB * NN];
__device__ float g_r_s2[NN * NN], g_r_c2[NN * NN], g_r_he[NN * NN], g_r_hp[NN * NN];
__device__ float g_s_s2[NS * NN], g_s_c2[NS * NN], g_s_he[NS * NN], g_s_hp[NS * NN];
__device__ float g_cmt[NN], g_Aj[NN], g_Dj[NN];

__device__ __forceinline__ float ex2f(float x) { float y; asm("ex2.approx.f32 %0, %1;" : "=f"(y) : "f"(x)); return y; }
__device__ __forceinline__ float rcpf(float x) { float y; asm("rcp.approx.f32 %0, %1;" : "=f"(y) : "f"(x)); return y; }
__device__ __forceinline__ uint32_t bf2pack(float x, float y) {
    uint32_t r; asm("cvt.rn.bf16x2.f32 %0, %1, %2;" : "=r"(r) : "f"(y), "f"(x)); return r;
}
__device__ __forceinline__ uint32_t smem_u32(const void* p) {
    uint32_t a;
    asm("{ .reg .u64 t; cvta.to.shared.u64 t, %1; cvt.u32.u64 %0, t; }" : "=r"(a) : "l"(p));
    return a;
}
__device__ __forceinline__ void ldm_x4(uint32_t* r, uint32_t addr) {
    asm volatile("ldmatrix.sync.aligned.m8n8.x4.shared.b16 {%0,%1,%2,%3}, [%4];"
                 : "=r"(r[0]), "=r"(r[1]), "=r"(r[2]), "=r"(r[3]) : "r"(addr));
}
__device__ __forceinline__ void mma16816(float* c, const uint32_t* a, uint32_t b0, uint32_t b1) {
    asm volatile("mma.sync.aligned.m16n8k16.row.col.f32.bf16.bf16.f32 "
                 "{%0,%1,%2,%3}, {%4,%5,%6,%7}, {%8,%9}, {%0,%1,%2,%3};"
                 : "+f"(c[0]), "+f"(c[1]), "+f"(c[2]), "+f"(c[3])
                 : "r"(a[0]), "r"(a[1]), "r"(a[2]), "r"(a[3]), "r"(b0), "r"(b1));
}

__global__ void precompute_kernel(
    const float* __restrict__ w_, const float* __restrict__ mu_, const float* __restrict__ sig_,
    const float* __restrict__ erev_, const float* __restrict__ mask_,
    const float* __restrict__ sw, const float* __restrict__ smu, const float* __restrict__ ssig,
    const float* __restrict__ serev, const float* __restrict__ smask,
    const float* __restrict__ gleak, const float* __restrict__ vleak, const float* __restrict__ cm_)
{
    int t = threadIdx.x;
    if (t < NN * NN) {
        float wp = log1pf(expf(w_[t])) * mask_[t];
        g_r_s2[t] = -sig_[t] * L2E;
        g_r_c2[t] = sig_[t] * mu_[t] * L2E;
        g_r_he[t] = wp * erev_[t];
        g_r_hp[t] = wp;
    }
    if (t < NS * NN) {
        float sp = log1pf(expf(sw[t]));
        g_s_s2[t] = -ssig[t] * L2E;
        g_s_c2[t] = ssig[t] * smu[t] * L2E;
        g_s_he[t] = sp * serev[t];
        g_s_hp[t] = sp * smask[t];
    }
    if (t < NN) {
        float cmt = log1pf(expf(cm_[t])) * (float)UNFOLDS;
        float g = log1pf(expf(gleak[t]));
        g_cmt[t] = cmt;
        g_Aj[t] = g * vleak[t];
        g_Dj[t] = cmt + g + 1e-8f;
    }
}

__global__ __launch_bounds__(256) void bsplit_kernel(const float* __restrict__ fc1w) {
    int row = blockIdx.x;
    for (int k = threadIdx.x; k < KP; k += 256) {
        float v = (k < K1) ? fc1w[(size_t)row * K1 + k] : 0.f;
        __nv_bfloat16 h = __float2bfloat16(v);
        __nv_bfloat16 l = __float2bfloat16(v - __bfloat162float(h));
        g_bh[(size_t)row * KP + k] = h;
        g_bl[(size_t)row * KP + k] = l;
    }
}

// conv 2x2 + ELU; each thread computes 2 adjacent outputs and writes u32-paired hi/lo
__global__ __launch_bounds__(256) void conv_kernel(
    const float* __restrict__ x, const float* __restrict__ cw, const float* __restrict__ cb)
{
    __shared__ float sx[CIN * HH * WWID];
    __shared__ float swt[COUT * CIN * 4];
    __shared__ float sb[COUT];
    int b = blockIdx.x;
    const float* xb = x + (size_t)b * (CIN * HH * WWID);
    for (int i = threadIdx.x; i < CIN * HH * WWID; i += 256) sx[i] = xb[i];
    if (threadIdx.x < COUT * CIN * 4) swt[threadIdx.x] = cw[threadIdx.x];
    if (threadIdx.x < COUT) sb[threadIdx.x] = cb[threadIdx.x];
    __syncthreads();
    __nv_bfloat16* oh = g_ah + (size_t)b * KP;
    __nv_bfloat16* ol = g_al + (size_t)b * KP;
    for (int idx2 = threadIdx.x; idx2 < (COUT * OH * OW) / 2; idx2 += 256) {
        float yv[2];
        #pragma unroll
        for (int q = 0; q < 2; q++) {
            int idx = 2 * idx2 + q;
            int c = idx / (OH * OW);
            int rem = idx - c * (OH * OW);
            int r = rem / OW;
            int col = rem - r * OW;
            float acc = sb[c];
            #pragma unroll
            for (int ci = 0; ci < CIN; ci++)
                #pragma unroll
                for (int kh = 0; kh < 2; kh++)
                    #pragma unroll
                    for (int kw = 0; kw < 2; kw++)
                        acc = fmaf(sx[ci * (HH * WWID) + (r + kh) * WWID + col + kw],
                                   swt[((c * CIN + ci) * 2 + kh) * 2 + kw], acc);
            yv[q] = acc > 0.f ? acc : expm1f(acc);
        }
        uint32_t hp = bf2pack(yv[0], yv[1]);
        __nv_bfloat162 hb = *reinterpret_cast<__nv_bfloat162*>(&hp);
        uint32_t lp = bf2pack(yv[0] - __bfloat162float(hb.x), yv[1] - __bfloat162float(hb.y));
        *(uint32_t*)(oh + 2 * idx2) = hp;
        *(uint32_t*)(ol + 2 * idx2) = lp;
    }
    if (threadIdx.x < (KP - K1) / 2) {   // zero pad
        *(uint32_t*)(oh + K1 + 2 * threadIdx.x) = 0u;
        *(uint32_t*)(ol + K1 + 2 * threadIdx.x) = 0u;
    }
}

// fc1 split-K GEMM: grid (128, SPLITK); writes fp32 partials (single-buffer, static smem)
__global__ __launch_bounds__(256) void gemm_kernel()
{
    __shared__ __align__(16) uint8_t sStage[4 * MT * SPB];   // 36,864 B

    const int tid = threadIdx.x;
    const int wid = tid >> 5;
    const int lid = tid & 31;
    const int wm = wid & 3;
    const int wn = wid >> 2;
    const int m0 = blockIdx.x * MT;
    const int c0 = blockIdx.y * CPS;
    const uint32_t sb = smem_u32(sStage);

    const uint32_t aRow = (uint32_t)((lid & 7) + 8 * ((lid >> 3) & 1));
    const uint32_t aOff = (uint32_t)((wm * 16 + aRow) * SPB + (lid >> 4) * 16);
    const uint32_t bRow0 = (uint32_t)(wn * 32 + (lid & 7) + 8 * (lid >> 4));
    const uint32_t bKh = (uint32_t)(((lid >> 3) & 1) * 16);
    const uint32_t bOff0 = bRow0 * SPB + bKh;
    const uint32_t bOff1 = (bRow0 + 16) * SPB + bKh;
    const uint32_t AH = sb, AL = sb + MT * SPB, BH = sb + 2 * MT * SPB, BL = sb + 3 * MT * SPB;

    int prow[2], po8[2];
    #pragma unroll
    for (int p = 0; p < 2; p++) { int id = tid + 256 * p; prow[p] = id >> 3; po8[p] = id & 7; }

    float acc[4][4];
    #pragma unroll
    for (int nb = 0; nb < 4; nb++)
        #pragma unroll
        for (int q = 0; q < 4; q++) acc[nb][q] = 0.f;

    uint4 rah[2], ral[2], rbh[2], rbl[2];
    auto ld_chunk = [&](int c) {
        #pragma unroll
        for (int p = 0; p < 2; p++) {
            size_t ga = (size_t)(m0 + prow[p]) * KP + c * 64 + po8[p] * 8;
            size_t gb = (size_t)prow[p] * KP + c * 64 + po8[p] * 8;
            rah[p] = *(const uint4*)(g_ah + ga);
            ral[p] = *(const uint4*)(g_al + ga);
            rbh[p] = *(const uint4*)(g_bh + gb);
            rbl[p] = *(const uint4*)(g_bl + gb);
        }
    };

    ld_chunk(c0);
    for (int ci = 0; ci < CPS; ++ci) {
        #pragma unroll
        for (int p = 0; p < 2; p++) {
            uint32_t so = (uint32_t)(prow[p] * SPB + po8[p] * 16);
            *(uint4*)(sStage + so) = rah[p];
            *(uint4*)(sStage + MT * SPB + so) = ral[p];
            *(uint4*)(sStage + 2 * MT * SPB + so) = rbh[p];
            *(uint4*)(sStage + 3 * MT * SPB + so) = rbl[p];
        }
        __syncthreads();
        if (ci + 1 < CPS) ld_chunk(c0 + ci + 1);
        #pragma unroll
        for (int s = 0; s < 4; ++s) {
            const uint32_t ks = (uint32_t)(32 * s);
            uint32_t ah[4], al[4], bh[8], bl[8];
            ldm_x4(ah, AH + aOff + ks);
            ldm_x4(al, AL + aOff + ks);
            ldm_x4(bh, BH + bOff0 + ks);
            ldm_x4(bh + 4, BH + bOff1 + ks);
            ldm_x4(bl, BL + bOff0 + ks);
            ldm_x4(bl + 4, BL + bOff1 + ks);
            #pragma unroll
            for (int nb = 0; nb < 4; ++nb) {
                mma16816(acc[nb], ah, bh[2 * nb], bh[2 * nb + 1]);
                mma16816(acc[nb], ah, bl[2 * nb], bl[2 * nb + 1]);
                mma16816(acc[nb], al, bh[2 * nb], bh[2 * nb + 1]);
            }
        }
        __syncthreads();
    }

    {
        int gid = lid >> 2, tig = lid & 3;
        int r0 = wm * 16 + gid;
        float* pb = g_part + ((size_t)blockIdx.y * TB + m0) * NF1;
        #pragma unroll
        for (int nb = 0; nb < 4; ++nb) {
            int col = wn * 32 + nb * 8 + 2 * tig;
            *(float2*)(pb + (size_t)r0 * NF1 + col) = make_float2(acc[nb][0], acc[nb][1]);
            *(float2*)(pb + (size_t)(r0 + 8) * NF1 + col) = make_float2(acc[nb][2], acc[nb][3]);
        }
    }
}

// epilogue: sum partials -> relu(fc1) -> fc2 -> input affine -> sensory synapses
__global__ __launch_bounds__(256) void epi_kernel(
    const float* __restrict__ fc1b,
    const float* __restrict__ fc2w, const float* __restrict__ fc2b,
    const float* __restrict__ inw, const float* __restrict__ inb)
{
    __shared__ float sAcc[64 * 68];
    __shared__ float sS[64 * 33];
    __shared__ float sF2[NS * NF1];
    __shared__ float sSm[160];
    __shared__ float sp[4 * NS * NN];

    const int tid = threadIdx.x;
    const int m0 = blockIdx.x * 64;

    for (int i = tid; i < NS * NF1; i += 256) sF2[i] = fc2w[i];
    if (tid < 64) sSm[tid] = fc1b[tid];
    if (tid < 32) { sSm[64 + tid] = fc2b[tid]; sSm[96 + tid] = inw[tid]; sSm[128 + tid] = inb[tid]; }
    for (int i = tid; i < NS * NN; i += 256) {
        sp[i] = g_s_s2[i];
        sp[NS * NN + i] = g_s_c2[i];
        sp[2 * NS * NN + i] = g_s_he[i];
        sp[3 * NS * NN + i] = g_s_hp[i];
    }

    for (int idx = tid; idx < 64 * 16; idx += 256) {
        int row = idx >> 4, c4 = (idx & 15) * 4;
        float4 a = make_float4(0.f, 0.f, 0.f, 0.f);
        #pragma unroll
        for (int s = 0; s < SPLITK; s++) {
            float4 v = *(const float4*)(g_part + ((size_t)s * TB + m0 + row) * NF1 + c4);
            a.x += v.x; a.y += v.y; a.z += v.z; a.w += v.w;
        }
        sAcc[row * 68 + c4 + 0] = fmaxf(a.x + sSm[c4 + 0], 0.f);
        sAcc[row * 68 + c4 + 1] = fmaxf(a.y + sSm[c4 + 1], 0.f);
        sAcc[row * 68 + c4 + 2] = fmaxf(a.z + sSm[c4 + 2], 0.f);
        sAcc[row * 68 + c4 + 3] = fmaxf(a.w + sSm[c4 + 3], 0.f);
    }
    __syncthreads();

    {
        int row = tid >> 2, cg = tid & 3;
        #pragma unroll
        for (int q = 0; q < 8; q++) {
            int n2 = cg * 8 + q;
            float a = sSm[64 + n2];
            #pragma unroll
            for (int n = 0; n < 64; n++) a = fmaf(sAcc[row * 68 + n], sF2[n2 * 64 + n], a);
            sS[row * 33 + n2] = fmaf(a, sSm[96 + n2], sSm[128 + n2]);
        }
    }
    __syncthreads();

    {
        int row2 = tid & 63, jg = tid >> 6;
        for (int jj = 0; jj < 5; jj++) {
            int j = jg * 5 + jj;
            if (j < NN) {
                float wn = 0.f, wd = 0.f;
                #pragma unroll
                for (int s2 = 0; s2 < NS; s2++) {
                    float he = sp[2 * NS * NN + s2 * NN + j];
                    float hp = sp[3 * NS * NN + s2 * NN + j];
                    if (he == 0.f && hp == 0.f) continue;
                    float e = ex2f(fmaf(sS[row2 * 33 + s2], sp[s2 * NN + j], sp[NS * NN + s2 * NN + j]));
                    float rr = rcpf(1.f + e);
                    wn = fmaf(rr, he, wn);
                    wd = fmaf(rr, hp, wd);
                }
                g_wns[(size_t)(m0 + row2) * NN + j] = wn;
                g_wds[(size_t)(m0 + row2) * NN + j] = wd;
            }
        }
    }
}

// LTC scan: CHUNK=8, WARM=5 -> 13 serial steps per warp, 1024 warps
__global__ __launch_bounds__(128) void ltc_kernel(
    const float* __restrict__ outw, const float* __restrict__ outb, float* __restrict__ out)
{
    const int w = threadIdx.x >> 5;
    const int j = threadIdx.x & 31;
    const int jc = j < NN ? j : NN - 1;
    const int c = blockIdx.x * 4 + w;

    float s2n[NN], c2n[NN], he[NN], hp[NN];
    #pragma unroll
    for (int i = 0; i < NN; i++) {
        s2n[i] = g_r_s2[i * NN + jc];
        c2n[i] = g_r_c2[i * NN + jc];
        he[i] = g_r_he[i * NN + jc];
        hp[i] = g_r_hp[i * NN + jc];
    }
    const float cmt = g_cmt[jc], Aj = g_Aj[jc], Dj = g_Dj[jc];
    const float ow = outw[0], ob = outb[0];

    const int tout = c * CHUNK;
    int t0 = tout - WARM; if (t0 < 0) t0 = 0;
    const int tend = tout + CHUNK;

    float v = 0.f;
    float wns = g_wns[(size_t)t0 * NN + jc];
    float wds = g_wds[(size_t)t0 * NN + jc];

    for (int t = t0; t < tend; ++t) {
        float wns_n = 0.f, wds_n = 0.f;
        if (t + 1 < tend) {
            wns_n = g_wns[(size_t)(t + 1) * NN + jc];
            wds_n = g_wds[(size_t)(t + 1) * NN + jc];
        }
        #pragma unroll 1
        for (int u = 0; u < UNFOLDS; u++) {
            float wn = wns, wd = wds;
            #pragma unroll
            for (int i = 0; i < NN; i++) {
                float vi = __shfl_sync(0xffffffffu, v, i);
                float e = ex2f(fmaf(vi, s2n[i], c2n[i]));
                float r = rcpf(1.f + e);
                wn = fmaf(r, he[i], wn);
                wd = fmaf(r, hp[i], wd);
            }
            v = (fmaf(cmt, v, Aj) + wn) * rcpf(Dj + wd);
        }
        if (t >= tout && j == 0) out[t] = fmaf(v, ow, ob);
        wns = wns_n; wds = wds_n;
    }
}

extern "C" void kernel_launch(void* const* d_in, const int* in_sizes, int n_in,
                              void* d_out, int out_size) {
    const float* x      = (const float*)d_in[0];
    const float* conv_w = (const float*)d_in[1];
    const float* conv_b = (const float*)d_in[2];
    const float* fc1_w  = (const float*)d_in[3];
    const float* fc1_b  = (const float*)d_in[4];
    const float* fc2_w  = (const float*)d_in[5];
    const float* fc2_b  = (const float*)d_in[6];
    const float* inw    = (const float*)d_in[7];
    const float* inb    = (const float*)d_in[8];
    const float* sw     = (const float*)d_in[9];
    const float* smu    = (const float*)d_in[10];
    const float* ssig   = (const float*)d_in[11];
    const float* serev  = (const float*)d_in[12];
    const float* smask  = (const float*)d_in[13];
    const float* w_     = (const float*)d_in[14];
    const float* mu_    = (const float*)d_in[15];
    const float* sig_   = (const float*)d_in[16];
    const float* erev_  = (const float*)d_in[17];
    const float* mask_  = (const float*)d_in[18];
    const float* gleak  = (const float*)d_in[19];
    const float* vleak  = (const float*)d_in[20];
    const float* cm_    = (const float*)d_in[21];
    const float* outw   = (const float*)d_in[22];
    const float* outb   = (const float*)d_in[23];
    float* out = (float*)d_out;

    precompute_kernel<<<1, NS * NN>>>(w_, mu_, sig_, erev_, mask_,
                                      sw, smu, ssig, serev, smask,
                                      gleak, vleak, cm_);
    bsplit_kernel<<<NF1, 256>>>(fc1_w);
    conv_kernel<<<TB, 256>>>(x, conv_w, conv_b);
    gemm_kernel<<<dim3(TB / MT, SPLITK), 256>>>();
    epi_kernel<<<TB / 64, 256>>>(fc1_b, fc2_w, fc2_b, inw, inb);
    ltc_kernel<<<(TB / CHUNK) / 4, 128>>>(outw, outb, out);
}

// round 14
// speedup vs baseline: 1.2937x; 1.0745x over previous
#include <cuda_runtime.h>
#include <cuda_bf16.h>
#include <cstdint>
#include <cstddef>

#define TB      8192
#define CIN     3
#define HH      23
#define WWID    30
#define COUT    8
#define OH      22
#define OW      29
#define K1      5104
#define KP      5120
#define NF1     64
#define NS      32
#define NN      19
#define UNFOLDS 6
#define CHUNK   8
#define WARM    5
#define L2E     1.4426950408889634f

#define MT      64
#define NCHUNK  80
#define SPLITK  4
#define CPS     (NCHUNK / SPLITK)   // 20 chunks per split
#define SPB     144

__device__ __nv_bfloat16 g_ah[(size_t)TB * KP];
__device__ __nv_bfloat16 g_al[(size_t)TB * KP];
__device__ __nv_bfloat16 g_bh[(size_t)NF1 * KP];
__device__ __nv_bfloat16 g_bl[(size_t)NF1 * KP];
__device__ float g_part[(size_t)SPLITK * TB * NF1];
__device__ float g_wns[(size_t)TB * NN];
__device__ float g_wds[(size_t)TB * NN];
__device__ float g_r_s2[NN * NN], g_r_c2[NN * NN], g_r_he[NN * NN], g_r_hp[NN * NN];
__device__ float g_s_s2[NS * NN], g_s_c2[NS * NN], g_s_he[NS * NN], g_s_hp[NS * NN];
__device__ float g_cmt[NN], g_Aj[NN], g_Dj[NN];

__device__ __forceinline__ float ex2f(float x) { float y; asm("ex2.approx.f32 %0, %1;" : "=f"(y) : "f"(x)); return y; }
__device__ __forceinline__ float rcpf(float x) { float y; asm("rcp.approx.f32 %0, %1;" : "=f"(y) : "f"(x)); return y; }
__device__ __forceinline__ uint32_t bf2pack(float x, float y) {
    uint32_t r; asm("cvt.rn.bf16x2.f32 %0, %1, %2;" : "=r"(r) : "f"(y), "f"(x)); return r;
}
__device__ __forceinline__ uint32_t smem_u32(const void* p) {
    uint32_t a;
    asm("{ .reg .u64 t; cvta.to.shared.u64 t, %1; cvt.u32.u64 %0, t; }" : "=r"(a) : "l"(p));
    return a;
}
__device__ __forceinline__ void ldm_x4(uint32_t* r, uint32_t addr) {
    asm volatile("ldmatrix.sync.aligned.m8n8.x4.shared.b16 {%0,%1,%2,%3}, [%4];"
                 : "=r"(r[0]), "=r"(r[1]), "=r"(r[2]), "=r"(r[3]) : "r"(addr));
}
__device__ __forceinline__ void mma16816(float* c, const uint32_t* a, uint32_t b0, uint32_t b1) {
    asm volatile("mma.sync.aligned.m16n8k16.row.col.f32.bf16.bf16.f32 "
                 "{%0,%1,%2,%3}, {%4,%5,%6,%7}, {%8,%9}, {%0,%1,%2,%3};"
                 : "+f"(c[0]), "+f"(c[1]), "+f"(c[2]), "+f"(c[3])
                 : "r"(a[0]), "r"(a[1]), "r"(a[2]), "r"(a[3]), "r"(b0), "r"(b1));
}

// merged front kernel:
//   blocks [0, TB)            : conv 2x2 + fast ELU -> A hi/lo
//   blocks [TB, TB+NF1)       : B pre-split row (b - TB)
//   block  TB+NF1             : parameter precompute
__global__ __launch_bounds__(256) void front_kernel(
    const float* __restrict__ x, const float* __restrict__ cw, const float* __restrict__ cb,
    const float* __restrict__ fc1w,
    const float* __restrict__ w_, const float* __restrict__ mu_, const float* __restrict__ sig_,
    const float* __restrict__ erev_, const float* __restrict__ mask_,
    const float* __restrict__ sw, const float* __restrict__ smu, const float* __restrict__ ssig,
    const float* __restrict__ serev, const float* __restrict__ smask,
    const float* __restrict__ gleak, const float* __restrict__ vleak, const float* __restrict__ cm_)
{
    int b = blockIdx.x;
    if (b < TB) {
        __shared__ float sx[CIN * HH * WWID];
        __shared__ float swt[COUT * CIN * 4];
        __shared__ float sb[COUT];
        const float* xb = x + (size_t)b * (CIN * HH * WWID);
        for (int i = threadIdx.x; i < CIN * HH * WWID; i += 256) sx[i] = xb[i];
        if (threadIdx.x < COUT * CIN * 4) swt[threadIdx.x] = cw[threadIdx.x];
        if (threadIdx.x < COUT) sb[threadIdx.x] = cb[threadIdx.x];
        __syncthreads();
        __nv_bfloat16* oh = g_ah + (size_t)b * KP;
        __nv_bfloat16* ol = g_al + (size_t)b * KP;
        for (int idx2 = threadIdx.x; idx2 < (COUT * OH * OW) / 2; idx2 += 256) {
            float yv[2];
            #pragma unroll
            for (int q = 0; q < 2; q++) {
                int idx = 2 * idx2 + q;
                int c = idx / (OH * OW);
                int rem = idx - c * (OH * OW);
                int r = rem / OW;
                int col = rem - r * OW;
                float acc = sb[c];
                #pragma unroll
                for (int ci = 0; ci < CIN; ci++)
                    #pragma unroll
                    for (int kh = 0; kh < 2; kh++)
                        #pragma unroll
                        for (int kw = 0; kw < 2; kw++)
                            acc = fmaf(sx[ci * (HH * WWID) + (r + kh) * WWID + col + kw],
                                       swt[((c * CIN + ci) * 2 + kh) * 2 + kw], acc);
                // fast ELU: expm1(x) = 2^(x*log2e) - 1 (ex2.approx, err ~1e-7)
                yv[q] = acc > 0.f ? acc : (ex2f(acc * L2E) - 1.0f);
            }
            uint32_t hp = bf2pack(yv[0], yv[1]);
            __nv_bfloat162 hb = *reinterpret_cast<__nv_bfloat162*>(&hp);
            uint32_t lp = bf2pack(yv[0] - __bfloat162float(hb.x), yv[1] - __bfloat162float(hb.y));
            *(uint32_t*)(oh + 2 * idx2) = hp;
            *(uint32_t*)(ol + 2 * idx2) = lp;
        }
        if (threadIdx.x < (KP - K1) / 2) {
            *(uint32_t*)(oh + K1 + 2 * threadIdx.x) = 0u;
            *(uint32_t*)(ol + K1 + 2 * threadIdx.x) = 0u;
        }
    } else if (b < TB + NF1) {
        int row = b - TB;
        for (int k = threadIdx.x; k < KP; k += 256) {
            float v = (k < K1) ? fc1w[(size_t)row * K1 + k] : 0.f;
            __nv_bfloat16 h = __float2bfloat16(v);
            __nv_bfloat16 l = __float2bfloat16(v - __bfloat162float(h));
            g_bh[(size_t)row * KP + k] = h;
            g_bl[(size_t)row * KP + k] = l;
        }
    } else {
        for (int t = threadIdx.x; t < NN * NN; t += 256) {
            float wp = log1pf(expf(w_[t])) * mask_[t];
            g_r_s2[t] = -sig_[t] * L2E;
            g_r_c2[t] = sig_[t] * mu_[t] * L2E;
            g_r_he[t] = wp * erev_[t];
            g_r_hp[t] = wp;
        }
        for (int t = threadIdx.x; t < NS * NN; t += 256) {
            float sp = log1pf(expf(sw[t]));
            g_s_s2[t] = -ssig[t] * L2E;
            g_s_c2[t] = ssig[t] * smu[t] * L2E;
            g_s_he[t] = sp * serev[t];
            g_s_hp[t] = sp * smask[t];
        }
        for (int t = threadIdx.x; t < NN; t += 256) {
            float cmt = log1pf(expf(cm_[t])) * (float)UNFOLDS;
            float g = log1pf(expf(gleak[t]));
            g_cmt[t] = cmt;
            g_Aj[t] = g * vleak[t];
            g_Dj[t] = cmt + g + 1e-8f;
        }
    }
}

// fc1 split-K GEMM: grid (128, SPLITK); writes fp32 partials (single-buffer, static smem)
__global__ __launch_bounds__(256) void gemm_kernel()
{
    __shared__ __align__(16) uint8_t sStage[4 * MT * SPB];   // 36,864 B

    const int tid = threadIdx.x;
    const int wid = tid >> 5;
    const int lid = tid & 31;
    const int wm = wid & 3;
    const int wn = wid >> 2;
    const int m0 = blockIdx.x * MT;
    const int c0 = blockIdx.y * CPS;
    const uint32_t sb = smem_u32(sStage);

    const uint32_t aRow = (uint32_t)((lid & 7) + 8 * ((lid >> 3) & 1));
    const uint32_t aOff = (uint32_t)((wm * 16 + aRow) * SPB + (lid >> 4) * 16);
    const uint32_t bRow0 = (uint32_t)(wn * 32 + (lid & 7) + 8 * (lid >> 4));
    const uint32_t bKh = (uint32_t)(((lid >> 3) & 1) * 16);
    const uint32_t bOff0 = bRow0 * SPB + bKh;
    const uint32_t bOff1 = (bRow0 + 16) * SPB + bKh;
    const uint32_t AH = sb, AL = sb + MT * SPB, BH = sb + 2 * MT * SPB, BL = sb + 3 * MT * SPB;

    int prow[2], po8[2];
    #pragma unroll
    for (int p = 0; p < 2; p++) { int id = tid + 256 * p; prow[p] = id >> 3; po8[p] = id & 7; }

    float acc[4][4];
    #pragma unroll
    for (int nb = 0; nb < 4; nb++)
        #pragma unroll
        for (int q = 0; q < 4; q++) acc[nb][q] = 0.f;

    uint4 rah[2], ral[2], rbh[2], rbl[2];
    auto ld_chunk = [&](int c) {
        #pragma unroll
        for (int p = 0; p < 2; p++) {
            size_t ga = (size_t)(m0 + prow[p]) * KP + c * 64 + po8[p] * 8;
            size_t gb = (size_t)prow[p] * KP + c * 64 + po8[p] * 8;
            rah[p] = *(const uint4*)(g_ah + ga);
            ral[p] = *(const uint4*)(g_al + ga);
            rbh[p] = *(const uint4*)(g_bh + gb);
            rbl[p] = *(const uint4*)(g_bl + gb);
        }
    };

    ld_chunk(c0);
    for (int ci = 0; ci < CPS; ++ci) {
        #pragma unroll
        for (int p = 0; p < 2; p++) {
            uint32_t so = (uint32_t)(prow[p] * SPB + po8[p] * 16);
            *(uint4*)(sStage + so) = rah[p];
            *(uint4*)(sStage + MT * SPB + so) = ral[p];
            *(uint4*)(sStage + 2 * MT * SPB + so) = rbh[p];
            *(uint4*)(sStage + 3 * MT * SPB + so) = rbl[p];
        }
        __syncthreads();
        if (ci + 1 < CPS) ld_chunk(c0 + ci + 1);
        #pragma unroll
        for (int s = 0; s < 4; ++s) {
            const uint32_t ks = (uint32_t)(32 * s);
            uint32_t ah[4], al[4], bh[8], bl[8];
            ldm_x4(ah, AH + aOff + ks);
            ldm_x4(al, AL + aOff + ks);
            ldm_x4(bh, BH + bOff0 + ks);
            ldm_x4(bh + 4, BH + bOff1 + ks);
            ldm_x4(bl, BL + bOff0 + ks);
            ldm_x4(bl + 4, BL + bOff1 + ks);
            #pragma unroll
            for (int nb = 0; nb < 4; ++nb) {
                mma16816(acc[nb], ah, bh[2 * nb], bh[2 * nb + 1]);
                mma16816(acc[nb], ah, bl[2 * nb], bl[2 * nb + 1]);
                mma16816(acc[nb], al, bh[2 * nb], bh[2 * nb + 1]);
            }
        }
        __syncthreads();
    }

    {
        int gid = lid >> 2, tig = lid & 3;
        int r0 = wm * 16 + gid;
        float* pb = g_part + ((size_t)blockIdx.y * TB + m0) * NF1;
        #pragma unroll
        for (int nb = 0; nb < 4; ++nb) {
            int col = wn * 32 + nb * 8 + 2 * tig;
            *(float2*)(pb + (size_t)r0 * NF1 + col) = make_float2(acc[nb][0], acc[nb][1]);
            *(float2*)(pb + (size_t)(r0 + 8) * NF1 + col) = make_float2(acc[nb][2], acc[nb][3]);
        }
    }
}

// epilogue: sum partials -> relu(fc1) -> fc2 -> input affine -> sensory synapses
// sF2 row stride 66 kills the 4-way LDS bank conflict (stride 64 ≡ 0 mod 32).
__global__ __launch_bounds__(256) void epi_kernel(
    const float* __restrict__ fc1b,
    const float* __restrict__ fc2w, const float* __restrict__ fc2b,
    const float* __restrict__ inw, const float* __restrict__ inb)
{
    __shared__ float sAcc[64 * 68];
    __shared__ float sS[64 * 33];
    __shared__ float sF2[NS * 66];
    __shared__ float sSm[160];
    __shared__ float sp[4 * NS * NN];

    const int tid = threadIdx.x;
    const int m0 = blockIdx.x * 64;

    for (int i = tid; i < NS * NF1; i += 256) sF2[(i >> 6) * 66 + (i & 63)] = fc2w[i];
    if (tid < 64) sSm[tid] = fc1b[tid];
    if (tid < 32) { sSm[64 + tid] = fc2b[tid]; sSm[96 + tid] = inw[tid]; sSm[128 + tid] = inb[tid]; }
    for (int i = tid; i < NS * NN; i += 256) {
        sp[i] = g_s_s2[i];
        sp[NS * NN + i] = g_s_c2[i];
        sp[2 * NS * NN + i] = g_s_he[i];
        sp[3 * NS * NN + i] = g_s_hp[i];
    }

    for (int idx = tid; idx < 64 * 16; idx += 256) {
        int row = idx >> 4, c4 = (idx & 15) * 4;
        float4 a = make_float4(0.f, 0.f, 0.f, 0.f);
        #pragma unroll
        for (int s = 0; s < SPLITK; s++) {
            float4 v = *(const float4*)(g_part + ((size_t)s * TB + m0 + row) * NF1 + c4);
            a.x += v.x; a.y += v.y; a.z += v.z; a.w += v.w;
        }
        sAcc[row * 68 + c4 + 0] = fmaxf(a.x + sSm[c4 + 0], 0.f);
        sAcc[row * 68 + c4 + 1] = fmaxf(a.y + sSm[c4 + 1], 0.f);
        sAcc[row * 68 + c4 + 2] = fmaxf(a.z + sSm[c4 + 2], 0.f);
        sAcc[row * 68 + c4 + 3] = fmaxf(a.w + sSm[c4 + 3], 0.f);
    }
    __syncthreads();

    {
        int row = tid >> 2, cg = tid & 3;
        #pragma unroll
        for (int q = 0; q < 8; q++) {
            int n2 = cg * 8 + q;
            float a = sSm[64 + n2];
            #pragma unroll
            for (int n = 0; n < 64; n++) a = fmaf(sAcc[row * 68 + n], sF2[n2 * 66 + n], a);
            sS[row * 33 + n2] = fmaf(a, sSm[96 + n2], sSm[128 + n2]);
        }
    }
    __syncthreads();

    {
        int row2 = tid & 63, jg = tid >> 6;
        for (int jj = 0; jj < 5; jj++) {
            int j = jg * 5 + jj;
            if (j < NN) {
                float wn = 0.f, wd = 0.f;
                #pragma unroll
                for (int s2 = 0; s2 < NS; s2++) {
                    float he = sp[2 * NS * NN + s2 * NN + j];
                    float hp = sp[3 * NS * NN + s2 * NN + j];
                    if (he == 0.f && hp == 0.f) continue;
                    float e = ex2f(fmaf(sS[row2 * 33 + s2], sp[s2 * NN + j], sp[NS * NN + s2 * NN + j]));
                    float rr = rcpf(1.f + e);
                    wn = fmaf(rr, he, wn);
                    wd = fmaf(rr, hp, wd);
                }
                g_wns[(size_t)(m0 + row2) * NN + j] = wn;
                g_wds[(size_t)(m0 + row2) * NN + j] = wd;
            }
        }
    }
}

// LTC scan: CHUNK=8, WARM=5 -> 13 serial steps per warp, 1024 warps
__global__ __launch_bounds__(128) void ltc_kernel(
    const float* __restrict__ outw, const float* __restrict__ outb, float* __restrict__ out)
{
    const int w = threadIdx.x >> 5;
    const int j = threadIdx.x & 31;
    const int jc = j < NN ? j : NN - 1;
    const int c = blockIdx.x * 4 + w;

    float s2n[NN], c2n[NN], he[NN], hp[NN];
    #pragma unroll
    for (int i = 0; i < NN; i++) {
        s2n[i] = g_r_s2[i * NN + jc];
        c2n[i] = g_r_c2[i * NN + jc];
        he[i] = g_r_he[i * NN + jc];
        hp[i] = g_r_hp[i * NN + jc];
    }
    const float cmt = g_cmt[jc], Aj = g_Aj[jc], Dj = g_Dj[jc];
    const float ow = outw[0], ob = outb[0];

    const int tout = c * CHUNK;
    int t0 = tout - WARM; if (t0 < 0) t0 = 0;
    const int tend = tout + CHUNK;

    float v = 0.f;
    float wns = g_wns[(size_t)t0 * NN + jc];
    float wds = g_wds[(size_t)t0 * NN + jc];

    for (int t = t0; t < tend; ++t) {
        float wns_n = 0.f, wds_n = 0.f;
        if (t + 1 < tend) {
            wns_n = g_wns[(size_t)(t + 1) * NN + jc];
            wds_n = g_wds[(size_t)(t + 1) * NN + jc];
        }
        #pragma unroll 1
        for (int u = 0; u < UNFOLDS; u++) {
            float wn = wns, wd = wds;
            #pragma unroll
            for (int i = 0; i < NN; i++) {
                float vi = __shfl_sync(0xffffffffu, v, i);
                float e = ex2f(fmaf(vi, s2n[i], c2n[i]));
                float r = rcpf(1.f + e);
                wn = fmaf(r, he[i], wn);
                wd = fmaf(r, hp[i], wd);
            }
            v = (fmaf(cmt, v, Aj) + wn) * rcpf(Dj + wd);
        }
        if (t >= tout && j == 0) out[t] = fmaf(v, ow, ob);
        wns = wns_n; wds = wds_n;
    }
}

extern "C" void kernel_launch(void* const* d_in, const int* in_sizes, int n_in,
                              void* d_out, int out_size) {
    const float* x      = (const float*)d_in[0];
    const float* conv_w = (const float*)d_in[1];
    const float* conv_b = (const float*)d_in[2];
    const float* fc1_w  = (const float*)d_in[3];
    const float* fc1_b  = (const float*)d_in[4];
    const float* fc2_w  = (const float*)d_in[5];
    const float* fc2_b  = (const float*)d_in[6];
    const float* inw    = (const float*)d_in[7];
    const float* inb    = (const float*)d_in[8];
    const float* sw     = (const float*)d_in[9];
    const float* smu    = (const float*)d_in[10];
    const float* ssig   = (const float*)d_in[11];
    const float* serev  = (const float*)d_in[12];
    const float* smask  = (const float*)d_in[13];
    const float* w_     = (const float*)d_in[14];
    const float* mu_    = (const float*)d_in[15];
    const float* sig_   = (const float*)d_in[16];
    const float* erev_  = (const float*)d_in[17];
    const float* mask_  = (const float*)d_in[18];
    const float* gleak  = (const float*)d_in[19];
    const float* vleak  = (const float*)d_in[20];
    const float* cm_    = (const float*)d_in[21];
    const float* outw   = (const float*)d_in[22];
    const float* outb   = (const float*)d_in[23];
    float* out = (float*)d_out;

    front_kernel<<<TB + NF1 + 1, 256>>>(x, conv_w, conv_b, fc1_w,
                                        w_, mu_, sig_, erev_, mask_,
                                        sw, smu, ssig, serev, smask,
                                        gleak, vleak, cm_);
    gemm_kernel<<<dim3(TB / MT, SPLITK), 256>>>();
    epi_kernel<<<TB / 64, 256>>>(fc1_b, fc2_w, fc2_b, inw, inb);
    ltc_kernel<<<(TB / CHUNK) / 4, 128>>>(outw, outb, out);
}